// round 2
// baseline (speedup 1.0000x reference)
#include <cuda_runtime.h>
#include <cstdint>

#define SCALE_LOGIT 7.2134752044448169f   // TEMP(5) * log2(e)

// ----------------- device scratch (no allocation allowed) -----------------
__device__ __align__(16) float d_Wtp[512 * 128];     // [k=ic*4+p*2+q][oc]; oc<64: theta(scaled), oc>=64: phi
__device__ __align__(16) float d_btp[128];           // theta bias (scaled) | phi bias
__device__ __align__(16) float d_Wg[512 * 64];       // [k][oc]
__device__ __align__(16) float d_bg[64];
__device__ __align__(16) float d_W2[64 * 512];       // [c2][oc*4+p*2+q]
__device__ __align__(16) float d_theta[4 * 64 * 9216]; // [b][c][n]   scaled logits
__device__ __align__(16) float d_phi[4 * 64 * 2304];   // [b][c][m]
__device__ __align__(16) float d_g[4 * 2304 * 64];     // [b][m][c]
__device__ __align__(16) float d_omap[4 * 64 * 9216];  // [b][c][n]

__device__ __forceinline__ float ex2f(float x) {
    float r; asm("ex2.approx.f32 %0, %1;" : "=f"(r) : "f"(x)); return r;
}

// ----------------- K1a: fuse theta/phi with down0 -----------------
__global__ void fuse_tp(const float* __restrict__ theta_w, const float* __restrict__ phi_w,
                        const float* __restrict__ down_w, const float* __restrict__ down_b) {
    int idx = blockIdx.x * 256 + threadIdx.x;   // 16384
    int oc = idx & 127, ic = idx >> 7;
    const float* wrow = (oc < 64) ? (theta_w + oc * 128) : (phi_w + (oc - 64) * 128);
    float a0 = 0.f, a1 = 0.f, a2 = 0.f, a3 = 0.f, ab = 0.f;
    for (int c = 0; c < 128; c++) {
        float wv = wrow[c];
        float4 dv = *(const float4*)(down_w + (size_t)(c * 128 + ic) * 4);
        a0 += wv * dv.x; a1 += wv * dv.y; a2 += wv * dv.z; a3 += wv * dv.w;
        if (ic == 0) ab += wv * down_b[c];
    }
    float s = (oc < 64) ? SCALE_LOGIT : 1.f;
    d_Wtp[(ic * 4 + 0) * 128 + oc] = a0 * s;
    d_Wtp[(ic * 4 + 1) * 128 + oc] = a1 * s;
    d_Wtp[(ic * 4 + 2) * 128 + oc] = a2 * s;
    d_Wtp[(ic * 4 + 3) * 128 + oc] = a3 * s;
    if (ic == 0) d_btp[oc] = ab * s;
}

// ----------------- K1b: fuse g with down1 -----------------
__global__ void fuse_g(const float* __restrict__ g_w,
                       const float* __restrict__ down_w, const float* __restrict__ down_b) {
    int idx = blockIdx.x * 256 + threadIdx.x;   // 8192
    int oc = idx & 63, ic = idx >> 6;
    const float* wrow = g_w + oc * 128;
    float a0 = 0.f, a1 = 0.f, a2 = 0.f, a3 = 0.f, ab = 0.f;
    for (int c = 0; c < 128; c++) {
        float wv = wrow[c];
        float4 dv = *(const float4*)(down_w + (size_t)(c * 128 + ic) * 4);
        a0 += wv * dv.x; a1 += wv * dv.y; a2 += wv * dv.z; a3 += wv * dv.w;
        if (ic == 0) ab += wv * down_b[c];
    }
    d_Wg[(ic * 4 + 0) * 64 + oc] = a0;
    d_Wg[(ic * 4 + 1) * 64 + oc] = a1;
    d_Wg[(ic * 4 + 2) * 64 + oc] = a2;
    d_Wg[(ic * 4 + 3) * 64 + oc] = a3;
    if (ic == 0) d_bg[oc] = ab;
}

// ----------------- K1c: fuse o_w with up_w -----------------
__global__ void fuse_w2(const float* __restrict__ o_w, const float* __restrict__ up_w) {
    int idx = blockIdx.x * 256 + threadIdx.x;   // 8192
    int c2 = idx & 63, oc = idx >> 6;
    float a0 = 0.f, a1 = 0.f, a2 = 0.f, a3 = 0.f;
    for (int och = 0; och < 128; och++) {
        float wv = o_w[och * 64 + c2];
        float4 dv = *(const float4*)(up_w + (size_t)(och * 128 + oc) * 4);
        a0 += wv * dv.x; a1 += wv * dv.y; a2 += wv * dv.z; a3 += wv * dv.w;
    }
    d_W2[c2 * 512 + oc * 4 + 0] = a0;
    d_W2[c2 * 512 + oc * 4 + 1] = a1;
    d_W2[c2 * 512 + oc * 4 + 2] = a2;
    d_W2[c2 * 512 + oc * 4 + 3] = a3;
}

// ----------------- K2: fused theta+phi conv (2x2/s2, K=512) + phi maxpool -----------------
// grid (3, 48, 4), 256 threads; tile = 2 out-rows x 32 out-cols, 128 out-ch
__global__ __launch_bounds__(256) void conv_tp(const float* __restrict__ X) {
    __shared__ float As[32 * 64];    // [k_local][px = r*32 + jc]
    __shared__ float Ws[32 * 128];   // [k_local][oc]
    int b = blockIdx.z, tr = blockIdx.y, tc = blockIdx.x;
    int tid = threadIdx.x;
    int og = tid & 15, pg = tid >> 4;
    float acc[4][8];
    #pragma unroll
    for (int i = 0; i < 4; i++)
        #pragma unroll
        for (int u = 0; u < 8; u++) acc[i][u] = 0.f;
    const float* Xb = X + (size_t)b * 128 * 192 * 192;
    int lane = tid & 31;
    int seg0 = (tid >> 5) * 4;
    for (int icb = 0; icb < 16; icb++) {
        for (int i = tid; i < 1024; i += 256)
            ((float4*)Ws)[i] = ((const float4*)(d_Wtp + icb * 4096))[i];
        #pragma unroll
        for (int s = 0; s < 4; s++) {
            int sg = seg0 + s;                      // ic8*4 + r*2 + p
            int ic8 = sg >> 2, r = (sg >> 1) & 1, p = sg & 1;
            int ic = icb * 8 + ic8;
            int irow = 4 * tr + 2 * r + p;
            float2 v = ((const float2*)(Xb + ((size_t)ic * 192 + irow) * 192 + tc * 64))[lane];
            int kb = ic8 * 4 + p * 2;
            As[(kb + 0) * 64 + r * 32 + lane] = v.x;
            As[(kb + 1) * 64 + r * 32 + lane] = v.y;
        }
        __syncthreads();
        #pragma unroll 4
        for (int k = 0; k < 32; k++) {
            const float* Ar = As + k * 64;
            float2 a01 = *(const float2*)(Ar + 2 * pg);
            float2 a23 = *(const float2*)(Ar + 32 + 2 * pg);
            const float* Wr = Ws + k * 128 + og * 8;
            float4 w0 = *(const float4*)(Wr);
            float4 w1 = *(const float4*)(Wr + 4);
            float wv[8] = {w0.x, w0.y, w0.z, w0.w, w1.x, w1.y, w1.z, w1.w};
            #pragma unroll
            for (int u = 0; u < 8; u++) {
                acc[0][u] += a01.x * wv[u];
                acc[1][u] += a01.y * wv[u];
                acc[2][u] += a23.x * wv[u];
                acc[3][u] += a23.y * wv[u];
            }
        }
        __syncthreads();
    }
    int i0 = tr * 2, j0 = tc * 32 + 2 * pg;
    if (og < 8) {  // theta (scaled): [b][c][n]
        #pragma unroll
        for (int u = 0; u < 8; u++) {
            int c = og * 8 + u;
            float bb = d_btp[c];
            float* dst = d_theta + ((size_t)b * 64 + c) * 9216;
            dst[(i0 + 0) * 96 + j0 + 0] = acc[0][u] + bb;
            dst[(i0 + 0) * 96 + j0 + 1] = acc[1][u] + bb;
            dst[(i0 + 1) * 96 + j0 + 0] = acc[2][u] + bb;
            dst[(i0 + 1) * 96 + j0 + 1] = acc[3][u] + bb;
        }
    } else {       // phi, maxpooled 2x2: [b][c][m]
        int m = tr * 48 + tc * 16 + pg;
        #pragma unroll
        for (int u = 0; u < 8; u++) {
            int c = (og - 8) * 8 + u;
            float v = fmaxf(fmaxf(acc[0][u], acc[1][u]), fmaxf(acc[2][u], acc[3][u])) + d_btp[64 + c];
            d_phi[((size_t)b * 64 + c) * 2304 + m] = v;
        }
    }
}

// ----------------- K3: fused g conv (2x2/s2, K=512) + maxpool -----------------
__global__ __launch_bounds__(256) void conv_g(const float* __restrict__ Y) {
    __shared__ float As[32 * 64];
    __shared__ float Ws[32 * 64];
    int b = blockIdx.z, tr = blockIdx.y, tc = blockIdx.x;
    int tid = threadIdx.x;
    int og = tid & 15, pg = tid >> 4;
    float acc[4][4];
    #pragma unroll
    for (int i = 0; i < 4; i++)
        #pragma unroll
        for (int u = 0; u < 4; u++) acc[i][u] = 0.f;
    const float* Yb = Y + (size_t)b * 128 * 192 * 192;
    int lane = tid & 31;
    int seg0 = (tid >> 5) * 4;
    for (int icb = 0; icb < 16; icb++) {
        for (int i = tid; i < 512; i += 256)
            ((float4*)Ws)[i] = ((const float4*)(d_Wg + icb * 2048))[i];
        #pragma unroll
        for (int s = 0; s < 4; s++) {
            int sg = seg0 + s;
            int ic8 = sg >> 2, r = (sg >> 1) & 1, p = sg & 1;
            int ic = icb * 8 + ic8;
            int irow = 4 * tr + 2 * r + p;
            float2 v = ((const float2*)(Yb + ((size_t)ic * 192 + irow) * 192 + tc * 64))[lane];
            int kb = ic8 * 4 + p * 2;
            As[(kb + 0) * 64 + r * 32 + lane] = v.x;
            As[(kb + 1) * 64 + r * 32 + lane] = v.y;
        }
        __syncthreads();
        #pragma unroll 4
        for (int k = 0; k < 32; k++) {
            const float* Ar = As + k * 64;
            float2 a01 = *(const float2*)(Ar + 2 * pg);
            float2 a23 = *(const float2*)(Ar + 32 + 2 * pg);
            float4 w = *(const float4*)(Ws + k * 64 + og * 4);
            float wv[4] = {w.x, w.y, w.z, w.w};
            #pragma unroll
            for (int u = 0; u < 4; u++) {
                acc[0][u] += a01.x * wv[u];
                acc[1][u] += a01.y * wv[u];
                acc[2][u] += a23.x * wv[u];
                acc[3][u] += a23.y * wv[u];
            }
        }
        __syncthreads();
    }
    int m = tr * 48 + tc * 16 + pg;   // pooled index, g: [b][m][c]
    float4 o;
    o.x = fmaxf(fmaxf(acc[0][0], acc[1][0]), fmaxf(acc[2][0], acc[3][0])) + d_bg[og * 4 + 0];
    o.y = fmaxf(fmaxf(acc[0][1], acc[1][1]), fmaxf(acc[2][1], acc[3][1])) + d_bg[og * 4 + 1];
    o.z = fmaxf(fmaxf(acc[0][2], acc[1][2]), fmaxf(acc[2][2], acc[3][2])) + d_bg[og * 4 + 2];
    o.w = fmaxf(fmaxf(acc[0][3], acc[1][3]), fmaxf(acc[2][3], acc[3][3])) + d_bg[og * 4 + 3];
    *(float4*)(d_g + ((size_t)b * 2304 + m) * 64 + og * 4) = o;
}

// ----------------- K4: flash attention (Br=64, Bc=32, C=64) -----------------
__global__ __launch_bounds__(256) void attn_k() {
    __shared__ float Qs[64 * 64];   // [c][q]
    __shared__ float Ks[64 * 32];   // [c][k]
    __shared__ float Gs[32 * 64];   // [k][c]
    __shared__ float Ps[64 * 36];   // [q][k]  (pad 36)
    int b = blockIdx.y;
    int n0 = blockIdx.x * 64;
    int tid = threadIdx.x;
    int qy = tid >> 4, kx = tid & 15;
    for (int i = tid; i < 1024; i += 256) {
        int c = i >> 4, q4 = i & 15;
        ((float4*)Qs)[i] = *(const float4*)(d_theta + ((size_t)b * 64 + c) * 9216 + n0 + q4 * 4);
    }
    float m_r[4], l_r[4], O[4][4];
    #pragma unroll
    for (int q = 0; q < 4; q++) {
        m_r[q] = -1e30f; l_r[q] = 0.f;
        #pragma unroll
        for (int cc = 0; cc < 4; cc++) O[q][cc] = 0.f;
    }
    __syncthreads();
    for (int it = 0; it < 72; it++) {
        int m0 = it * 32;
        for (int i = tid; i < 512; i += 256) {
            int c = i >> 3, k4 = i & 7;
            ((float4*)Ks)[i] = *(const float4*)(d_phi + ((size_t)b * 64 + c) * 2304 + m0 + k4 * 4);
        }
        for (int i = tid; i < 512; i += 256)
            ((float4*)Gs)[i] = ((const float4*)(d_g + ((size_t)b * 2304 + m0) * 64))[i];
        __syncthreads();
        float S[4][2];
        #pragma unroll
        for (int q = 0; q < 4; q++) { S[q][0] = 0.f; S[q][1] = 0.f; }
        #pragma unroll 8
        for (int c = 0; c < 64; c++) {
            float4 qv = *(const float4*)(Qs + c * 64 + qy * 4);
            float2 kv = *(const float2*)(Ks + c * 32 + kx * 2);
            S[0][0] += qv.x * kv.x; S[0][1] += qv.x * kv.y;
            S[1][0] += qv.y * kv.x; S[1][1] += qv.y * kv.y;
            S[2][0] += qv.z * kv.x; S[2][1] += qv.z * kv.y;
            S[3][0] += qv.w * kv.x; S[3][1] += qv.w * kv.y;
        }
        float al[4];
        #pragma unroll
        for (int q = 0; q < 4; q++) {
            float mt = fmaxf(S[q][0], S[q][1]);
            mt = fmaxf(mt, __shfl_xor_sync(0xffffffffu, mt, 1));
            mt = fmaxf(mt, __shfl_xor_sync(0xffffffffu, mt, 2));
            mt = fmaxf(mt, __shfl_xor_sync(0xffffffffu, mt, 4));
            mt = fmaxf(mt, __shfl_xor_sync(0xffffffffu, mt, 8));
            float mn = fmaxf(m_r[q], mt);
            al[q] = ex2f(m_r[q] - mn);
            m_r[q] = mn;
            S[q][0] = ex2f(S[q][0] - mn);
            S[q][1] = ex2f(S[q][1] - mn);
            float rs = S[q][0] + S[q][1];
            rs += __shfl_xor_sync(0xffffffffu, rs, 1);
            rs += __shfl_xor_sync(0xffffffffu, rs, 2);
            rs += __shfl_xor_sync(0xffffffffu, rs, 4);
            rs += __shfl_xor_sync(0xffffffffu, rs, 8);
            l_r[q] = l_r[q] * al[q] + rs;
        }
        #pragma unroll
        for (int q = 0; q < 4; q++)
            *(float2*)(Ps + (qy * 4 + q) * 36 + kx * 2) = make_float2(S[q][0], S[q][1]);
        __syncthreads();
        #pragma unroll
        for (int q = 0; q < 4; q++)
            #pragma unroll
            for (int cc = 0; cc < 4; cc++) O[q][cc] *= al[q];
        #pragma unroll
        for (int k = 0; k < 32; k += 4) {
            float4 g0 = *(const float4*)(Gs + (k + 0) * 64 + kx * 4);
            float4 g1 = *(const float4*)(Gs + (k + 1) * 64 + kx * 4);
            float4 g2 = *(const float4*)(Gs + (k + 2) * 64 + kx * 4);
            float4 g3 = *(const float4*)(Gs + (k + 3) * 64 + kx * 4);
            #pragma unroll
            for (int q = 0; q < 4; q++) {
                float4 p = *(const float4*)(Ps + (qy * 4 + q) * 36 + k);
                O[q][0] += p.x * g0.x + p.y * g1.x + p.z * g2.x + p.w * g3.x;
                O[q][1] += p.x * g0.y + p.y * g1.y + p.z * g2.y + p.w * g3.y;
                O[q][2] += p.x * g0.z + p.y * g1.z + p.z * g2.z + p.w * g3.z;
                O[q][3] += p.x * g0.w + p.y * g1.w + p.z * g2.w + p.w * g3.w;
            }
        }
        __syncthreads();
    }
    float inv[4];
    #pragma unroll
    for (int q = 0; q < 4; q++) inv[q] = 1.f / l_r[q];
    #pragma unroll
    for (int cc = 0; cc < 4; cc++) {
        float4 v = make_float4(O[0][cc] * inv[0], O[1][cc] * inv[1],
                               O[2][cc] * inv[2], O[3][cc] * inv[3]);
        *(float4*)(d_omap + ((size_t)b * 64 + kx * 4 + cc) * 9216 + n0 + qy * 4) = v;
    }
}

// ----------------- K5: fused (o_w o up) + bias + gamma*y, coalesced out -----------------
// grid (3, 48, 16): z = b*4 + ocb ; dynamic smem 49152B
__global__ __launch_bounds__(256) void out_k(const float* __restrict__ Y,
                                             const float* __restrict__ up_b,
                                             const float* __restrict__ gammap,
                                             float* __restrict__ out) {
    extern __shared__ float sm[];
    float* Os = sm;           // [c2][px] 64*64
    float* Ws = sm + 4096;    // [c2][row] 64*128 ; later reused as 32x4x64 staging
    int tc = blockIdx.x, tr = blockIdx.y;
    int b = blockIdx.z >> 2, ocb = blockIdx.z & 3;
    int tid = threadIdx.x;
    int og = tid & 15, pg = tid >> 4;
    for (int i = tid; i < 2048; i += 256) {
        int c2 = i >> 5, r4 = i & 31;
        ((float4*)Ws)[i] = *(const float4*)(d_W2 + c2 * 512 + ocb * 128 + r4 * 4);
    }
    for (int i = tid; i < 1024; i += 256) {
        int c2 = i >> 4, s4 = i & 15;
        int r = s4 >> 3, jc = (s4 & 7) * 4;
        ((float4*)Os)[i] = *(const float4*)(d_omap + ((size_t)b * 64 + c2) * 9216
                                            + (2 * tr + r) * 96 + tc * 32 + jc);
    }
    __syncthreads();
    float acc[4][8];
    #pragma unroll
    for (int i = 0; i < 4; i++)
        #pragma unroll
        for (int u = 0; u < 8; u++) acc[i][u] = 0.f;
    #pragma unroll 4
    for (int c2 = 0; c2 < 64; c2++) {
        const float* Ar = Os + c2 * 64;
        float2 a01 = *(const float2*)(Ar + 2 * pg);
        float2 a23 = *(const float2*)(Ar + 32 + 2 * pg);
        const float* Wr = Ws + c2 * 128 + og * 8;
        float4 w0 = *(const float4*)(Wr);
        float4 w1 = *(const float4*)(Wr + 4);
        float wv[8] = {w0.x, w0.y, w0.z, w0.w, w1.x, w1.y, w1.z, w1.w};
        #pragma unroll
        for (int u = 0; u < 8; u++) {
            acc[0][u] += a01.x * wv[u];
            acc[1][u] += a01.y * wv[u];
            acc[2][u] += a23.x * wv[u];
            acc[3][u] += a23.y * wv[u];
        }
    }
    __syncthreads();
    float* stg = Ws;   // 32 oc x 4 lrow x 64 col
    #pragma unroll
    for (int u = 0; u < 8; u++) {
        int row = og * 8 + u;
        int oc_l = row >> 2, p = (row >> 1) & 1, q = row & 1;
        #pragma unroll
        for (int px = 0; px < 4; px++) {
            int r = px >> 1;
            int jc = 2 * pg + (px & 1);
            stg[oc_l * 256 + (2 * r + p) * 64 + 2 * jc + q] = acc[px][u];
        }
    }
    __syncthreads();
    float gamma = *gammap;
    for (int i = tid; i < 2048; i += 256) {
        int col4 = i & 15, lrow = (i >> 4) & 3, oc_l = i >> 6;
        int oc = ocb * 32 + oc_l;
        size_t gaddr = (((size_t)b * 128 + oc) * 192 + (4 * tr + lrow)) * 192 + tc * 64 + col4 * 4;
        float4 s = ((float4*)stg)[oc_l * 64 + lrow * 16 + col4];
        float4 yv = *(const float4*)(Y + gaddr);
        float bb = up_b[oc];
        float4 o = make_float4(s.x + bb + gamma * yv.x, s.y + bb + gamma * yv.y,
                               s.z + bb + gamma * yv.z, s.w + bb + gamma * yv.w);
        *(float4*)(out + gaddr) = o;
    }
}

// ----------------- launch -----------------
extern "C" void kernel_launch(void* const* d_in, const int* in_sizes, int n_in,
                              void* d_out, int out_size) {
    (void)in_sizes; (void)n_in; (void)out_size;
    const float* input_x = (const float*)d_in[0];
    const float* input_y = (const float*)d_in[1];
    const float* down0_w = (const float*)d_in[2];
    const float* down0_b = (const float*)d_in[3];
    const float* down1_w = (const float*)d_in[4];
    const float* down1_b = (const float*)d_in[5];
    const float* theta_w = (const float*)d_in[6];
    const float* phi_w   = (const float*)d_in[7];
    const float* g_w     = (const float*)d_in[8];
    const float* o_w     = (const float*)d_in[9];
    const float* up_w    = (const float*)d_in[10];
    const float* up_b    = (const float*)d_in[11];
    const float* gamma   = (const float*)d_in[12];
    float* out = (float*)d_out;

    fuse_tp<<<64, 256>>>(theta_w, phi_w, down0_w, down0_b);
    fuse_g<<<32, 256>>>(g_w, down1_w, down1_b);
    fuse_w2<<<32, 256>>>(o_w, up_w);
    conv_tp<<<dim3(3, 48, 4), 256>>>(input_x);
    conv_g<<<dim3(3, 48, 4), 256>>>(input_y);
    attn_k<<<dim3(144, 4), 256>>>();
    out_k<<<dim3(3, 48, 16), 256, 49152>>>(input_y, up_b, gamma, out);
}

// round 5
// speedup vs baseline: 1.5166x; 1.5166x over previous
#include <cuda_runtime.h>
#include <cstdint>

#define SCALE_LOGIT 7.2134752044448169f   // TEMP(5) * log2(e)

// ----------------- device scratch (no allocation allowed) -----------------
__device__ __align__(16) float d_Wtp[512 * 128];     // [k=ic*4+p*2+q][oc]; oc<64: theta(scaled), oc>=64: phi
__device__ __align__(16) float d_btp[128];           // theta bias (scaled) | phi bias
__device__ __align__(16) float d_Wg[512 * 64];       // [k][oc]
__device__ __align__(16) float d_bg[64];
__device__ __align__(16) float d_W2[64 * 512];       // [c2][oc*4+p*2+q]
__device__ __align__(16) float d_theta_hi[4 * 64 * 9216]; // [b][c][n] scaled logits, tf32 hi
__device__ __align__(16) float d_theta_lo[4 * 64 * 9216]; // [b][c][n] tf32 lo
__device__ __align__(16) float d_phi_hi[4 * 2304 * 64];   // [b][m][c] tf32 hi (key-major)
__device__ __align__(16) float d_phi_lo[4 * 2304 * 64];   // [b][m][c] tf32 lo
__device__ __align__(16) float d_g[4 * 2304 * 64];        // [b][m][c] tf32-rounded
__device__ __align__(16) float d_omap[4 * 64 * 9216];     // [b][c][n]

__device__ __forceinline__ float ex2f(float x) {
    float r; asm("ex2.approx.f32 %0, %1;" : "=f"(r) : "f"(x)); return r;
}
__device__ __forceinline__ float tf32r(float x) {
    uint32_t u; asm("cvt.rna.tf32.f32 %0, %1;" : "=r"(u) : "f"(x)); return __uint_as_float(u);
}
__device__ __forceinline__ void mma_tf32(float* c, const uint32_t* a, uint32_t b0, uint32_t b1) {
    asm volatile("mma.sync.aligned.m16n8k8.row.col.f32.tf32.tf32.f32 "
                 "{%0,%1,%2,%3},{%4,%5,%6,%7},{%8,%9},{%0,%1,%2,%3};"
                 : "+f"(c[0]), "+f"(c[1]), "+f"(c[2]), "+f"(c[3])
                 : "r"(a[0]), "r"(a[1]), "r"(a[2]), "r"(a[3]), "r"(b0), "r"(b1));
}

// ----------------- K1a: fuse theta/phi with down0 -----------------
__global__ void fuse_tp(const float* __restrict__ theta_w, const float* __restrict__ phi_w,
                        const float* __restrict__ down_w, const float* __restrict__ down_b) {
    int idx = blockIdx.x * 256 + threadIdx.x;   // 16384
    int oc = idx & 127, ic = idx >> 7;
    const float* wrow = (oc < 64) ? (theta_w + oc * 128) : (phi_w + (oc - 64) * 128);
    float a0 = 0.f, a1 = 0.f, a2 = 0.f, a3 = 0.f, ab = 0.f;
    for (int c = 0; c < 128; c++) {
        float wv = wrow[c];
        float4 dv = *(const float4*)(down_w + (size_t)(c * 128 + ic) * 4);
        a0 += wv * dv.x; a1 += wv * dv.y; a2 += wv * dv.z; a3 += wv * dv.w;
        if (ic == 0) ab += wv * down_b[c];
    }
    float s = (oc < 64) ? SCALE_LOGIT : 1.f;
    d_Wtp[(ic * 4 + 0) * 128 + oc] = a0 * s;
    d_Wtp[(ic * 4 + 1) * 128 + oc] = a1 * s;
    d_Wtp[(ic * 4 + 2) * 128 + oc] = a2 * s;
    d_Wtp[(ic * 4 + 3) * 128 + oc] = a3 * s;
    if (ic == 0) d_btp[oc] = ab * s;
}

// ----------------- K1b: fuse g with down1 -----------------
__global__ void fuse_g(const float* __restrict__ g_w,
                       const float* __restrict__ down_w, const float* __restrict__ down_b) {
    int idx = blockIdx.x * 256 + threadIdx.x;   // 8192
    int oc = idx & 63, ic = idx >> 6;
    const float* wrow = g_w + oc * 128;
    float a0 = 0.f, a1 = 0.f, a2 = 0.f, a3 = 0.f, ab = 0.f;
    for (int c = 0; c < 128; c++) {
        float wv = wrow[c];
        float4 dv = *(const float4*)(down_w + (size_t)(c * 128 + ic) * 4);
        a0 += wv * dv.x; a1 += wv * dv.y; a2 += wv * dv.z; a3 += wv * dv.w;
        if (ic == 0) ab += wv * down_b[c];
    }
    d_Wg[(ic * 4 + 0) * 64 + oc] = a0;
    d_Wg[(ic * 4 + 1) * 64 + oc] = a1;
    d_Wg[(ic * 4 + 2) * 64 + oc] = a2;
    d_Wg[(ic * 4 + 3) * 64 + oc] = a3;
    if (ic == 0) d_bg[oc] = ab;
}

// ----------------- K1c: fuse o_w with up_w -----------------
__global__ void fuse_w2(const float* __restrict__ o_w, const float* __restrict__ up_w) {
    int idx = blockIdx.x * 256 + threadIdx.x;   // 8192
    int c2 = idx & 63, oc = idx >> 6;
    float a0 = 0.f, a1 = 0.f, a2 = 0.f, a3 = 0.f;
    for (int och = 0; och < 128; och++) {
        float wv = o_w[och * 64 + c2];
        float4 dv = *(const float4*)(up_w + (size_t)(och * 128 + oc) * 4);
        a0 += wv * dv.x; a1 += wv * dv.y; a2 += wv * dv.z; a3 += wv * dv.w;
    }
    d_W2[c2 * 512 + oc * 4 + 0] = a0;
    d_W2[c2 * 512 + oc * 4 + 1] = a1;
    d_W2[c2 * 512 + oc * 4 + 2] = a2;
    d_W2[c2 * 512 + oc * 4 + 3] = a3;
}

// ----------------- K2: fused theta+phi conv (2x2/s2, K=512) + phi maxpool -----------------
// grid (3, 48, 4), 256 threads; tile = 2 out-rows x 32 out-cols, 128 out-ch
__global__ __launch_bounds__(256) void conv_tp(const float* __restrict__ X) {
    __shared__ float As[32 * 64];    // [k_local][px = r*32 + jc]
    __shared__ float Ws[32 * 128];   // [k_local][oc]
    int b = blockIdx.z, tr = blockIdx.y, tc = blockIdx.x;
    int tid = threadIdx.x;
    int og = tid & 15, pg = tid >> 4;
    float acc[4][8];
    #pragma unroll
    for (int i = 0; i < 4; i++)
        #pragma unroll
        for (int u = 0; u < 8; u++) acc[i][u] = 0.f;
    const float* Xb = X + (size_t)b * 128 * 192 * 192;
    int lane = tid & 31;
    int seg0 = (tid >> 5) * 4;
    for (int icb = 0; icb < 16; icb++) {
        for (int i = tid; i < 1024; i += 256)
            ((float4*)Ws)[i] = ((const float4*)(d_Wtp + icb * 4096))[i];
        #pragma unroll
        for (int s = 0; s < 4; s++) {
            int sg = seg0 + s;                      // ic8*4 + r*2 + p
            int ic8 = sg >> 2, r = (sg >> 1) & 1, p = sg & 1;
            int ic = icb * 8 + ic8;
            int irow = 4 * tr + 2 * r + p;
            float2 v = ((const float2*)(Xb + ((size_t)ic * 192 + irow) * 192 + tc * 64))[lane];
            int kb = ic8 * 4 + p * 2;
            As[(kb + 0) * 64 + r * 32 + lane] = v.x;
            As[(kb + 1) * 64 + r * 32 + lane] = v.y;
        }
        __syncthreads();
        #pragma unroll 4
        for (int k = 0; k < 32; k++) {
            const float* Ar = As + k * 64;
            float2 a01 = *(const float2*)(Ar + 2 * pg);
            float2 a23 = *(const float2*)(Ar + 32 + 2 * pg);
            const float* Wr = Ws + k * 128 + og * 8;
            float4 w0 = *(const float4*)(Wr);
            float4 w1 = *(const float4*)(Wr + 4);
            float wv[8] = {w0.x, w0.y, w0.z, w0.w, w1.x, w1.y, w1.z, w1.w};
            #pragma unroll
            for (int u = 0; u < 8; u++) {
                acc[0][u] += a01.x * wv[u];
                acc[1][u] += a01.y * wv[u];
                acc[2][u] += a23.x * wv[u];
                acc[3][u] += a23.y * wv[u];
            }
        }
        __syncthreads();
    }
    int i0 = tr * 2, j0 = tc * 32 + 2 * pg;
    if (og < 8) {  // theta (scaled): hi/lo split, [b][c][n]
        #pragma unroll
        for (int u = 0; u < 8; u++) {
            int c = og * 8 + u;
            float bb = d_btp[c];
            float* dh = d_theta_hi + ((size_t)b * 64 + c) * 9216;
            float* dl = d_theta_lo + ((size_t)b * 64 + c) * 9216;
            int o00 = (i0 + 0) * 96 + j0, o10 = (i0 + 1) * 96 + j0;
            float v0 = acc[0][u] + bb, v1 = acc[1][u] + bb;
            float v2 = acc[2][u] + bb, v3 = acc[3][u] + bb;
            float h0 = tf32r(v0), h1 = tf32r(v1), h2 = tf32r(v2), h3 = tf32r(v3);
            dh[o00] = h0; dh[o00 + 1] = h1; dh[o10] = h2; dh[o10 + 1] = h3;
            dl[o00] = tf32r(v0 - h0); dl[o00 + 1] = tf32r(v1 - h1);
            dl[o10] = tf32r(v2 - h2); dl[o10 + 1] = tf32r(v3 - h3);
        }
    } else {       // phi, maxpooled 2x2: hi/lo split, key-major [b][m][c]
        int m = tr * 48 + tc * 16 + pg;
        #pragma unroll
        for (int u = 0; u < 8; u++) {
            int c = (og - 8) * 8 + u;
            float v = fmaxf(fmaxf(acc[0][u], acc[1][u]), fmaxf(acc[2][u], acc[3][u])) + d_btp[64 + c];
            float h = tf32r(v);
            size_t addr = ((size_t)b * 2304 + m) * 64 + c;
            d_phi_hi[addr] = h;
            d_phi_lo[addr] = tf32r(v - h);
        }
    }
}

// ----------------- K3: fused g conv (2x2/s2, K=512) + maxpool -----------------
__global__ __launch_bounds__(256) void conv_g(const float* __restrict__ Y) {
    __shared__ float As[32 * 64];
    __shared__ float Ws[32 * 64];
    int b = blockIdx.z, tr = blockIdx.y, tc = blockIdx.x;
    int tid = threadIdx.x;
    int og = tid & 15, pg = tid >> 4;
    float acc[4][4];
    #pragma unroll
    for (int i = 0; i < 4; i++)
        #pragma unroll
        for (int u = 0; u < 4; u++) acc[i][u] = 0.f;
    const float* Yb = Y + (size_t)b * 128 * 192 * 192;
    int lane = tid & 31;
    int seg0 = (tid >> 5) * 4;
    for (int icb = 0; icb < 16; icb++) {
        for (int i = tid; i < 512; i += 256)
            ((float4*)Ws)[i] = ((const float4*)(d_Wg + icb * 2048))[i];
        #pragma unroll
        for (int s = 0; s < 4; s++) {
            int sg = seg0 + s;
            int ic8 = sg >> 2, r = (sg >> 1) & 1, p = sg & 1;
            int ic = icb * 8 + ic8;
            int irow = 4 * tr + 2 * r + p;
            float2 v = ((const float2*)(Yb + ((size_t)ic * 192 + irow) * 192 + tc * 64))[lane];
            int kb = ic8 * 4 + p * 2;
            As[(kb + 0) * 64 + r * 32 + lane] = v.x;
            As[(kb + 1) * 64 + r * 32 + lane] = v.y;
        }
        __syncthreads();
        #pragma unroll 4
        for (int k = 0; k < 32; k++) {
            const float* Ar = As + k * 64;
            float2 a01 = *(const float2*)(Ar + 2 * pg);
            float2 a23 = *(const float2*)(Ar + 32 + 2 * pg);
            float4 w = *(const float4*)(Ws + k * 64 + og * 4);
            float wv[4] = {w.x, w.y, w.z, w.w};
            #pragma unroll
            for (int u = 0; u < 4; u++) {
                acc[0][u] += a01.x * wv[u];
                acc[1][u] += a01.y * wv[u];
                acc[2][u] += a23.x * wv[u];
                acc[3][u] += a23.y * wv[u];
            }
        }
        __syncthreads();
    }
    int m = tr * 48 + tc * 16 + pg;   // pooled index, g: [b][m][c], tf32-rounded
    float4 o;
    o.x = tf32r(fmaxf(fmaxf(acc[0][0], acc[1][0]), fmaxf(acc[2][0], acc[3][0])) + d_bg[og * 4 + 0]);
    o.y = tf32r(fmaxf(fmaxf(acc[0][1], acc[1][1]), fmaxf(acc[2][1], acc[3][1])) + d_bg[og * 4 + 1]);
    o.z = tf32r(fmaxf(fmaxf(acc[0][2], acc[1][2]), fmaxf(acc[2][2], acc[3][2])) + d_bg[og * 4 + 2]);
    o.w = tf32r(fmaxf(fmaxf(acc[0][3], acc[1][3]), fmaxf(acc[2][3], acc[3][3])) + d_bg[og * 4 + 3]);
    *(float4*)(d_g + ((size_t)b * 2304 + m) * 64 + og * 4) = o;
}

// ----------------- K4: tf32 tensor-core flash attention (Br=64, Bc=64, C=64) -----------------
// grid (144, 4), 128 threads (4 warps, one m16 q-row tile each)
__global__ __launch_bounds__(128) void attn_tc() {
    extern __shared__ float sm[];
    float* Khi = sm;                    // [64 key][68]
    float* Klo = sm + 4352;             // [64 key][68]
    float* Gs  = sm + 2 * 4352;         // [64 key][72]
    float* Ps  = sm + 2 * 4352 + 4608;  // [64 q][68]  (also reused as O staging [ch][q])
    int b = blockIdx.y;
    int n0 = blockIdx.x * 64;
    int tid = threadIdx.x;
    int w = tid >> 5, lane = tid & 31;
    int g = lane >> 2, tig = lane & 3;
    int qa = n0 + w * 16 + g, qb = qa + 8;

    // Q fragments for all 8 k-steps (hi and lo), held in registers for the whole kernel
    uint32_t Ahi[8][4], Alo[8][4];
    {
        const float* th = d_theta_hi + (size_t)b * 64 * 9216;
        const float* tl = d_theta_lo + (size_t)b * 64 * 9216;
        #pragma unroll
        for (int ks = 0; ks < 8; ks++) {
            int c0 = ks * 8 + tig, c1 = c0 + 4;
            Ahi[ks][0] = __float_as_uint(th[(size_t)c0 * 9216 + qa]);
            Ahi[ks][1] = __float_as_uint(th[(size_t)c0 * 9216 + qb]);
            Ahi[ks][2] = __float_as_uint(th[(size_t)c1 * 9216 + qa]);
            Ahi[ks][3] = __float_as_uint(th[(size_t)c1 * 9216 + qb]);
            Alo[ks][0] = __float_as_uint(tl[(size_t)c0 * 9216 + qa]);
            Alo[ks][1] = __float_as_uint(tl[(size_t)c0 * 9216 + qb]);
            Alo[ks][2] = __float_as_uint(tl[(size_t)c1 * 9216 + qa]);
            Alo[ks][3] = __float_as_uint(tl[(size_t)c1 * 9216 + qb]);
        }
    }
    float mA = -1e30f, mB = -1e30f, lA = 0.f, lB = 0.f;
    float O[8][4];
    #pragma unroll
    for (int nt = 0; nt < 8; nt++)
        #pragma unroll
        for (int u = 0; u < 4; u++) O[nt][u] = 0.f;

    const float* phb = d_phi_hi + (size_t)b * 2304 * 64;
    const float* plb = d_phi_lo + (size_t)b * 2304 * 64;
    const float* gb  = d_g     + (size_t)b * 2304 * 64;

    for (int it = 0; it < 36; it++) {
        int m0 = it * 64;
        __syncthreads();   // previous PV done before overwriting K/G
        for (int i = tid; i < 1024; i += 128) {
            int key = i >> 4, c4 = (i & 15) * 4;
            size_t src = (size_t)(m0 + key) * 64 + c4;
            *(float4*)(Khi + key * 68 + c4) = *(const float4*)(phb + src);
            *(float4*)(Klo + key * 68 + c4) = *(const float4*)(plb + src);
            *(float4*)(Gs  + key * 72 + c4) = *(const float4*)(gb  + src);
        }
        __syncthreads();
        // S = theta_tile @ phi_tile^T  (split tf32: hh + hl + lh)
        float S[8][4];
        #pragma unroll
        for (int nt = 0; nt < 8; nt++) {
            float* Sa = S[nt];
            Sa[0] = 0.f; Sa[1] = 0.f; Sa[2] = 0.f; Sa[3] = 0.f;
            const float* KH = Khi + (nt * 8 + g) * 68 + tig;
            const float* KL = Klo + (nt * 8 + g) * 68 + tig;
            #pragma unroll
            for (int ks = 0; ks < 8; ks++) {
                uint32_t bh0 = __float_as_uint(KH[ks * 8]);
                uint32_t bh1 = __float_as_uint(KH[ks * 8 + 4]);
                uint32_t bl0 = __float_as_uint(KL[ks * 8]);
                uint32_t bl1 = __float_as_uint(KL[ks * 8 + 4]);
                mma_tf32(Sa, Ahi[ks], bh0, bh1);
                mma_tf32(Sa, Ahi[ks], bl0, bl1);
                mma_tf32(Sa, Alo[ks], bh0, bh1);
            }
        }
        // online softmax (logits already in log2 domain)
        float mxA = -1e30f, mxB = -1e30f;
        #pragma unroll
        for (int nt = 0; nt < 8; nt++) {
            mxA = fmaxf(mxA, fmaxf(S[nt][0], S[nt][1]));
            mxB = fmaxf(mxB, fmaxf(S[nt][2], S[nt][3]));
        }
        mxA = fmaxf(mxA, __shfl_xor_sync(0xffffffffu, mxA, 1));
        mxA = fmaxf(mxA, __shfl_xor_sync(0xffffffffu, mxA, 2));
        mxB = fmaxf(mxB, __shfl_xor_sync(0xffffffffu, mxB, 1));
        mxB = fmaxf(mxB, __shfl_xor_sync(0xffffffffu, mxB, 2));
        float mnA = fmaxf(mA, mxA), mnB = fmaxf(mB, mxB);
        float aA = ex2f(mA - mnA), aB = ex2f(mB - mnB);
        mA = mnA; mB = mnB;
        float sumA = 0.f, sumB = 0.f;
        #pragma unroll
        for (int nt = 0; nt < 8; nt++) {
            S[nt][0] = ex2f(S[nt][0] - mA);
            S[nt][1] = ex2f(S[nt][1] - mA);
            S[nt][2] = ex2f(S[nt][2] - mB);
            S[nt][3] = ex2f(S[nt][3] - mB);
            sumA += S[nt][0] + S[nt][1];
            sumB += S[nt][2] + S[nt][3];
        }
        sumA += __shfl_xor_sync(0xffffffffu, sumA, 1);
        sumA += __shfl_xor_sync(0xffffffffu, sumA, 2);
        sumB += __shfl_xor_sync(0xffffffffu, sumB, 1);
        sumB += __shfl_xor_sync(0xffffffffu, sumB, 2);
        lA = lA * aA + sumA;
        lB = lB * aB + sumB;
        #pragma unroll
        for (int nt = 0; nt < 8; nt++) {
            O[nt][0] *= aA; O[nt][1] *= aA; O[nt][2] *= aB; O[nt][3] *= aB;
        }
        // store P (tf32-rounded) to per-warp rows of Ps
        int q0 = w * 16 + g;
        #pragma unroll
        for (int nt = 0; nt < 8; nt++) {
            int k0 = nt * 8 + 2 * tig;
            *(float2*)(Ps + q0 * 68 + k0)       = make_float2(tf32r(S[nt][0]), tf32r(S[nt][1]));
            *(float2*)(Ps + (q0 + 8) * 68 + k0) = make_float2(tf32r(S[nt][2]), tf32r(S[nt][3]));
        }
        __syncwarp();   // P rows are per-warp private
        // O += P @ G
        #pragma unroll
        for (int kt = 0; kt < 8; kt++) {
            uint32_t a[4];
            const float* PR = Ps + (size_t)(w * 16 + g) * 68 + kt * 8 + tig;
            a[0] = __float_as_uint(PR[0]);
            a[1] = __float_as_uint(PR[8 * 68]);
            a[2] = __float_as_uint(PR[4]);
            a[3] = __float_as_uint(PR[8 * 68 + 4]);
            const float* GR = Gs + (kt * 8 + tig) * 72 + g;
            #pragma unroll
            for (int nt = 0; nt < 8; nt++) {
                uint32_t b0 = __float_as_uint(GR[nt * 8]);
                uint32_t b1 = __float_as_uint(GR[4 * 72 + nt * 8]);
                mma_tf32(O[nt], a, b0, b1);
            }
        }
    }
    // normalize + transpose through smem + coalesced write to d_omap [b][c][n]
    __syncthreads();
    float ilA = 1.f / lA, ilB = 1.f / lB;
    int q0 = w * 16 + g;
    #pragma unroll
    for (int nt = 0; nt < 8; nt++) {
        int ch = nt * 8 + 2 * tig;
        Ps[ch * 68 + q0]           = O[nt][0] * ilA;
        Ps[(ch + 1) * 68 + q0]     = O[nt][1] * ilA;
        Ps[ch * 68 + q0 + 8]       = O[nt][2] * ilB;
        Ps[(ch + 1) * 68 + q0 + 8] = O[nt][3] * ilB;
    }
    __syncthreads();
    float* om = d_omap + (size_t)b * 64 * 9216 + n0;
    for (int i = tid; i < 1024; i += 128) {
        int ch = i >> 4, c4 = (i & 15) * 4;
        *(float4*)(om + (size_t)ch * 9216 + c4) = *(float4*)(Ps + ch * 68 + c4);
    }
}

// ----------------- K5: fused (o_w o up) + bias + gamma*y, coalesced out -----------------
// grid (3, 48, 16): z = b*4 + ocb ; dynamic smem 49152B
__global__ __launch_bounds__(256) void out_k(const float* __restrict__ Y,
                                             const float* __restrict__ up_b,
                                             const float* __restrict__ gammap,
                                             float* __restrict__ out) {
    extern __shared__ float sm[];
    float* Os = sm;           // [c2][px] 64*64
    float* Ws = sm + 4096;    // [c2][row] 64*128 ; later reused as 32x4x64 staging
    int tc = blockIdx.x, tr = blockIdx.y;
    int b = blockIdx.z >> 2, ocb = blockIdx.z & 3;
    int tid = threadIdx.x;
    int og = tid & 15, pg = tid >> 4;
    for (int i = tid; i < 2048; i += 256) {
        int c2 = i >> 5, r4 = i & 31;
        ((float4*)Ws)[i] = *(const float4*)(d_W2 + c2 * 512 + ocb * 128 + r4 * 4);
    }
    for (int i = tid; i < 1024; i += 256) {
        int c2 = i >> 4, s4 = i & 15;
        int r = s4 >> 3, jc = (s4 & 7) * 4;
        ((float4*)Os)[i] = *(const float4*)(d_omap + ((size_t)b * 64 + c2) * 9216
                                            + (2 * tr + r) * 96 + tc * 32 + jc);
    }
    __syncthreads();
    float acc[4][8];
    #pragma unroll
    for (int i = 0; i < 4; i++)
        #pragma unroll
        for (int u = 0; u < 8; u++) acc[i][u] = 0.f;
    #pragma unroll 4
    for (int c2 = 0; c2 < 64; c2++) {
        const float* Ar = Os + c2 * 64;
        float2 a01 = *(const float2*)(Ar + 2 * pg);
        float2 a23 = *(const float2*)(Ar + 32 + 2 * pg);
        const float* Wr = Ws + c2 * 128 + og * 8;
        float4 w0 = *(const float4*)(Wr);
        float4 w1 = *(const float4*)(Wr + 4);
        float wv[8] = {w0.x, w0.y, w0.z, w0.w, w1.x, w1.y, w1.z, w1.w};
        #pragma unroll
        for (int u = 0; u < 8; u++) {
            acc[0][u] += a01.x * wv[u];
            acc[1][u] += a01.y * wv[u];
            acc[2][u] += a23.x * wv[u];
            acc[3][u] += a23.y * wv[u];
        }
    }
    __syncthreads();
    float* stg = Ws;   // 32 oc x 4 lrow x 64 col
    #pragma unroll
    for (int u = 0; u < 8; u++) {
        int row = og * 8 + u;
        int oc_l = row >> 2, p = (row >> 1) & 1, q = row & 1;
        #pragma unroll
        for (int px = 0; px < 4; px++) {
            int r = px >> 1;
            int jc = 2 * pg + (px & 1);
            stg[oc_l * 256 + (2 * r + p) * 64 + 2 * jc + q] = acc[px][u];
        }
    }
    __syncthreads();
    float gamma = *gammap;
    for (int i = tid; i < 2048; i += 256) {
        int col4 = i & 15, lrow = (i >> 4) & 3, oc_l = i >> 6;
        int oc = ocb * 32 + oc_l;
        size_t gaddr = (((size_t)b * 128 + oc) * 192 + (4 * tr + lrow)) * 192 + tc * 64 + col4 * 4;
        float4 s = ((float4*)stg)[oc_l * 64 + lrow * 16 + col4];
        float4 yv = *(const float4*)(Y + gaddr);
        float bb = up_b[oc];
        float4 o = make_float4(s.x + bb + gamma * yv.x, s.y + bb + gamma * yv.y,
                               s.z + bb + gamma * yv.z, s.w + bb + gamma * yv.w);
        *(float4*)(out + gaddr) = o;
    }
}

// ----------------- launch -----------------
extern "C" void kernel_launch(void* const* d_in, const int* in_sizes, int n_in,
                              void* d_out, int out_size) {
    (void)in_sizes; (void)n_in; (void)out_size;
    const float* input_x = (const float*)d_in[0];
    const float* input_y = (const float*)d_in[1];
    const float* down0_w = (const float*)d_in[2];
    const float* down0_b = (const float*)d_in[3];
    const float* down1_w = (const float*)d_in[4];
    const float* down1_b = (const float*)d_in[5];
    const float* theta_w = (const float*)d_in[6];
    const float* phi_w   = (const float*)d_in[7];
    const float* g_w     = (const float*)d_in[8];
    const float* o_w     = (const float*)d_in[9];
    const float* up_w    = (const float*)d_in[10];
    const float* up_b    = (const float*)d_in[11];
    const float* gamma   = (const float*)d_in[12];
    float* out = (float*)d_out;

    cudaFuncSetAttribute(attn_tc, cudaFuncAttributeMaxDynamicSharedMemorySize, 70656);

    fuse_tp<<<64, 256>>>(theta_w, phi_w, down0_w, down0_b);
    fuse_g<<<32, 256>>>(g_w, down1_w, down1_b);
    fuse_w2<<<32, 256>>>(o_w, up_w);
    conv_tp<<<dim3(3, 48, 4), 256>>>(input_x);
    conv_g<<<dim3(3, 48, 4), 256>>>(input_y);
    attn_tc<<<dim3(144, 4), 128, 70656>>>();
    out_k<<<dim3(3, 48, 16), 256, 49152>>>(input_y, up_b, gamma, out);
}